// round 15
// baseline (speedup 1.0000x reference)
#include <cuda_runtime.h>
#include <cuda_fp16.h>
#include <cstdint>

// ============================================================================
// Problem constants
// ============================================================================
#define BB       512
#define TT       100          // K per batch
#define TPAD     112          // padded to 7 x k16
#define NPRE     256
#define NPOST    256
#define KTOT     (BB * TT)    // 51200
#define KSPLIT   148          // grid (148) = one CTA per SM, pure split-K

// A tile (trace fp16, [p][t]): 256 rows, stride 240B
#define A_ROW_B   240
#define A_TILE_B  (256 * A_ROW_B)       // 61440
// B tile (post fp16, [t][q]): 112 rows x 256 fp16, stride 528B
#define B_ROW_B   528
#define B_TILE_B  (TPAD * B_ROW_B)      // 59136
// pre staging (fp32, [t][p]): 100 rows x 256 f32, stride 264 floats (1056B)
//   (50*264 mod 32 == 16 -> seg0/seg1 LDS use disjoint bank halves)
#define STG_ROW_F 264
#define STG_ROW_B 1056
#define STG_B     (TT * STG_ROW_B)      // 105600

#define SM_A      0
#define SM_B      A_TILE_B                         // 61440
#define SM_STG    (A_TILE_B + B_TILE_B)            // 120576
#define GEMM_SMEM (SM_STG + STG_B)                 // 226176  (< 232448 cap)

// ============================================================================
// PTX helpers (baseline PTX only — tcgen05 unavailable on plain sm_103 target)
// ============================================================================
__device__ __forceinline__ void ldmatrix_x4(uint32_t* r, uint32_t addr) {
    asm volatile("ldmatrix.sync.aligned.m8n8.x4.shared.b16 {%0,%1,%2,%3}, [%4];"
                 : "=r"(r[0]), "=r"(r[1]), "=r"(r[2]), "=r"(r[3]) : "r"(addr));
}
__device__ __forceinline__ void ldmatrix_x4_trans(uint32_t* r, uint32_t addr) {
    asm volatile("ldmatrix.sync.aligned.m8n8.x4.trans.shared.b16 {%0,%1,%2,%3}, [%4];"
                 : "=r"(r[0]), "=r"(r[1]), "=r"(r[2]), "=r"(r[3]) : "r"(addr));
}
// fp16-accumulator MMA
__device__ __forceinline__ void mma_16816_f16(uint32_t* c, const uint32_t* a, const uint32_t* b) {
    asm volatile(
        "mma.sync.aligned.m16n8k16.row.col.f16.f16.f16.f16 "
        "{%0,%1}, {%2,%3,%4,%5}, {%6,%7}, {%0,%1};"
        : "+r"(c[0]), "+r"(c[1])
        : "r"(a[0]), "r"(a[1]), "r"(a[2]), "r"(a[3]), "r"(b[0]), "r"(b[1]));
}
__device__ __forceinline__ uint32_t smem_to_u32(const void* smem_ptr) {
    uint32_t addr;
    asm("{ .reg .u64 tmp; cvta.to.shared.u64 tmp, %1; cvt.u32.u64 %0, tmp; }"
        : "=r"(addr) : "l"(smem_ptr));
    return addr;
}
__device__ __forceinline__ void cp_async_16(uint32_t dst_smem, const void* src) {
    asm volatile("cp.async.cg.shared.global [%0], [%1], 16;"
                 :: "r"(dst_smem), "l"(src) : "memory");
}
#define CP_ASYNC_COMMIT() asm volatile("cp.async.commit_group;" ::: "memory")
#define CP_ASYNC_WAIT0()  asm volatile("cp.async.wait_group 0;" ::: "memory")

__device__ __forceinline__ uint32_t pack_f16x2(float a, float b) {
    __half2 h = __floats2half2_rn(a, b);
    return *(uint32_t*)&h;
}

// ============================================================================
// Kernel 0: zero the output (d_out is poisoned; atomics need a clean base)
// ============================================================================
__global__ void stdp_zero_kernel(float4* __restrict__ out) {
    out[blockIdx.x * blockDim.x + threadIdx.x] = make_float4(0.f, 0.f, 0.f, 0.f);
}

// ============================================================================
// Fused kernel: CTA tile 256x256 (whole batch per CTA), pure split-K grid 148.
//   cp.async pre staging + 2-segment shuffle-carry scan + latency-hidden post
//   convert + fp16-accum HMMA. 512 threads = 16 warps (4 M x 4 N), warp 64x64.
// ============================================================================
__global__ void __launch_bounds__(512, 1) stdp_fused_kernel(
    const float* __restrict__ pre, const float* __restrict__ post,
    float* __restrict__ out)
{
    extern __shared__ __align__(16) char smem[];
    const uint32_t su = smem_to_u32(smem);
    float* stg = (float*)(smem + SM_STG);      // [100][264] fp32 pre staging

    const int tid    = threadIdx.x;
    const int wid    = tid >> 5;
    const int lane   = tid & 31;
    const int kid    = blockIdx.x;             // split-K id, 0..147
    const int warp_m = wid >> 2;               // 0..3 (64 rows)
    const int warp_n = wid & 3;                // 0..3 (64 cols)

    // scan roles: one p's 2 segments (50 t each) live in ONE warp
    const int sp  = wid * 16 + (lane & 15);    // p in [0,256)
    const int seg = lane >> 4;                 // 0..1
    const int t0  = seg * 50;

    const float d = 0.95122942450071403f;      // exp(-1/20)

    // ---- zero pads once (prepare only writes t < 100) ----
    for (int i = tid; i < 256 * 6; i += 512) {            // A bytes [200,224)
        int row = i / 6, off = (i % 6) * 4;
        *(uint32_t*)(smem + SM_A + row * A_ROW_B + 200 + off) = 0u;
    }
    for (int i = tid; i < 12 * 128; i += 512) {           // B rows 100..111
        int row = 100 + i / 128, off = (i % 128) * 4;
        *(uint32_t*)(smem + SM_B + row * B_ROW_B + off) = 0u;
    }

    // fp16x2 accumulators: warp tile 64x64 -> [mi 4][ni 8][2]
    uint32_t acc[4][8][2];
    #pragma unroll
    for (int i = 0; i < 4; ++i)
        #pragma unroll
        for (int j = 0; j < 8; ++j) {
            acc[i][j][0] = 0u; acc[i][j][1] = 0u;
        }

    const int nb = (BB - kid + KSPLIT - 1) / KSPLIT;   // 3 or 4 batches

    // ---- cp.async: pre[b] tile [t][p] fp32 -> staging (full 256 p) ----
    auto issue_pre = [&](int b) {
        const float* src = pre + (size_t)b * TT * NPRE;
        #pragma unroll
        for (int it = 0; it < 13; ++it) {
            int f = tid + it * 512;
            if (f < 6400) {                     // 100 rows x 64 chunks of 16B
                int t = f >> 6, g = f & 63;
                cp_async_16(su + SM_STG + t * STG_ROW_B + g * 16,
                            src + (size_t)t * NPRE + g * 4);
            }
        }
        CP_ASYNC_COMMIT();
    };

    // post chunk load / store (float4 granularity, 6400 total, stride 512)
    auto ldg_post = [&](int b, float4* v, int it0, int cnt) {
        const float4* psrc = (const float4*)(post + (size_t)b * TT * NPOST);
        #pragma unroll
        for (int k = 0; k < 4; ++k) {
            if (k < cnt) {
                int f = tid + (it0 + k) * 512;
                if (f < 6400) v[k] = psrc[f];
            }
        }
    };
    auto sts_post = [&](const float4* v, int it0, int cnt) {
        #pragma unroll
        for (int k = 0; k < 4; ++k) {
            if (k < cnt) {
                int f = tid + (it0 + k) * 512;
                if (f < 6400) {
                    int t = f >> 6, qg = f & 63;
                    *(uint2*)(smem + SM_B + t * B_ROW_B + qg * 8) =
                        make_uint2(pack_f16x2(v[k].x, v[k].y), pack_f16x2(v[k].z, v[k].w));
                }
            }
        }
    };

    // ---- prepare(b): 2-seg shuffle-carry scan + latency-hidden post cvt ----
    auto prepare = [&](int b) {
        float4 v[4];
        float xr[26];

        // chunk 0 LDG (hides behind L-phase chain)
        ldg_post(b, v, 0, 4);

        // L phase, part 1 (t0 .. t0+25)
        #pragma unroll
        for (int i = 0; i < 26; ++i)
            xr[i] = stg[(t0 + i) * STG_ROW_F + sp];
        float L = 0.0f;
        #pragma unroll
        for (int i = 0; i < 26; ++i)
            L = d * (L + xr[i]);

        sts_post(v, 0, 4);
        ldg_post(b, v, 4, 4);

        // L phase, part 2 (t0+26 .. t0+49)
        #pragma unroll
        for (int i = 0; i < 24; ++i)
            xr[i] = stg[(t0 + 26 + i) * STG_ROW_F + sp];
        #pragma unroll
        for (int i = 0; i < 24; ++i)
            L = d * (L + xr[i]);

        sts_post(v, 4, 4);
        ldg_post(b, v, 8, 4);

        // carry: seg1 starts from seg0's local sum (seg0 starts at 0)
        float Cin = __shfl_up_sync(0xffffffffu, L, 16);
        float C = seg ? Cin : 0.0f;

        // emit part 1: reload t0..t0+25, write 13 packed pairs
        #pragma unroll
        for (int i = 0; i < 26; ++i)
            xr[i] = stg[(t0 + i) * STG_ROW_F + sp];
        char* arow = smem + SM_A + sp * A_ROW_B + t0 * 2;   // t0 even -> 4-aligned
        #pragma unroll
        for (int i = 0; i < 26; i += 2) {
            float c0 = C;
            C = d * (C + xr[i]);
            float c1 = C;
            C = d * (C + xr[i + 1]);
            *(uint32_t*)(arow + i * 2) = pack_f16x2(c0, c1);
        }

        sts_post(v, 8, 4);
        ldg_post(b, v, 12, 1);

        // emit part 2: reload t0+26..t0+49, write 12 packed pairs
        #pragma unroll
        for (int i = 0; i < 24; ++i)
            xr[i] = stg[(t0 + 26 + i) * STG_ROW_F + sp];
        #pragma unroll
        for (int i = 0; i < 24; i += 2) {
            float c0 = C;
            C = d * (C + xr[i]);
            float c1 = C;
            C = d * (C + xr[i + 1]);
            *(uint32_t*)(arow + (26 + i) * 2) = pack_f16x2(c0, c1);
        }

        sts_post(v, 12, 1);
    };

    // ---- prologue ----
    issue_pre(kid);
    CP_ASYNC_WAIT0();
    __syncthreads();          // pads + staging(0) ready
    prepare(kid);
    __syncthreads();

    // ldmatrix lane addressing
    const int a_row  = (lane & 15);
    const int a_colh = (lane >> 4) * 8;
    const int bg  = lane >> 3;
    const int bl8 = lane & 7;
    const int b_krow = (bg & 1) * 8 + bl8;
    const int b_qoff = (bg >> 1) * 8;

    const uint32_t A  = su + SM_A;
    const uint32_t Bb = su + SM_B;

    for (int j = 0; j < nb; ++j) {
        // prefetch next batch's pre (async, overlaps MMA below)
        if (j + 1 < nb)
            issue_pre(kid + (j + 1) * KSPLIT);

        // ---- MMA over 7 k16 steps (warp tile 64x64, fp16 accum) ----
        #pragma unroll
        for (int ks = 0; ks < 7; ++ks) {
            uint32_t afrag[4][4];
            uint32_t bfrag[8][2];
            #pragma unroll
            for (int mi = 0; mi < 4; ++mi) {
                uint32_t addr = A + (uint32_t)((warp_m * 64 + mi * 16 + a_row) * A_ROW_B
                                               + (a_colh + ks * 16) * 2);
                ldmatrix_x4(afrag[mi], addr);
            }
            #pragma unroll
            for (int nip = 0; nip < 4; ++nip) {
                uint32_t addr = Bb + (uint32_t)((ks * 16 + b_krow) * B_ROW_B
                                                + (warp_n * 64 + nip * 16 + b_qoff) * 2);
                uint32_t r[4];
                ldmatrix_x4_trans(r, addr);
                bfrag[nip * 2 + 0][0] = r[0]; bfrag[nip * 2 + 0][1] = r[1];
                bfrag[nip * 2 + 1][0] = r[2]; bfrag[nip * 2 + 1][1] = r[3];
            }
            #pragma unroll
            for (int mi = 0; mi < 4; ++mi)
                #pragma unroll
                for (int ni = 0; ni < 8; ++ni)
                    mma_16816_f16(acc[mi][ni], afrag[mi], bfrag[ni]);
        }

        // ---- build next batch's tiles ----
        if (j + 1 < nb) {
            CP_ASYNC_WAIT0();      // staging(j+1) landed
            __syncthreads();       // all warps done reading A/B of batch j
            prepare(kid + (j + 1) * KSPLIT);
            __syncthreads();       // tiles for j+1 visible
        }
    }

    // ---- epilogue: unpack fp16 acc, scale, RED atomics into d_out ----
    const float scale = (0.005f - 0.00525f) / (float)KTOT;
    const int p_base = warp_m * 64;
    const int q_base = warp_n * 64;
    #pragma unroll
    for (int mi = 0; mi < 4; ++mi) {
        #pragma unroll
        for (int ni = 0; ni < 8; ++ni) {
            int p0 = p_base + mi * 16 + (lane >> 2);
            int q  = q_base + ni * 8 + (lane & 3) * 2;
            float2 f0 = __half22float2(*(__half2*)&acc[mi][ni][0]);
            float2 f1 = __half22float2(*(__half2*)&acc[mi][ni][1]);
            float* o0 = out + (size_t)p0 * NPOST + q;
            float* o1 = out + (size_t)(p0 + 8) * NPOST + q;
            atomicAdd(o0,     f0.x * scale);
            atomicAdd(o0 + 1, f0.y * scale);
            atomicAdd(o1,     f1.x * scale);
            atomicAdd(o1 + 1, f1.y * scale);
        }
    }
}

// ============================================================================
// Launch
// ============================================================================
extern "C" void kernel_launch(void* const* d_in, const int* in_sizes, int n_in,
                              void* d_out, int out_size) {
    (void)in_sizes; (void)n_in; (void)out_size;
    const float* pre  = (const float*)d_in[0];
    const float* post = (const float*)d_in[1];
    float* out = (float*)d_out;

    cudaFuncSetAttribute(stdp_fused_kernel,
                         cudaFuncAttributeMaxDynamicSharedMemorySize, GEMM_SMEM);

    stdp_zero_kernel<<<64, 256>>>((float4*)out);   // 65536 floats
    stdp_fused_kernel<<<KSPLIT, 512, GEMM_SMEM>>>(pre, post, out);
}